// round 15
// baseline (speedup 1.0000x reference)
#include <cuda_runtime.h>
#include <cuda_bf16.h>
#include <cstdint>

#define D_DIM 128
#define MAX_NODES 50000
#define MAX_EDGES 800000
#define SMS 132        // padded smem row stride (floats)
#define TROWS 64       // A-tile rows per gemm tile
#define GEMM_GRID 304  // 2 CTAs/SM * 152 SMs
#define SCAN_CHUNK 1024

__device__ int   g_count[MAX_NODES];
__device__ int   g_offset[MAX_NODES + 1];
__device__ int   g_cursor[MAX_NODES];
__device__ int   g_elist[MAX_EDGES];   // src ids grouped by dst
__device__ int   g_bsum[64];
__device__ int   g_idx64;
__device__ int   g_ticket;

// ---------------------------------------------------------------------------
// Init: zero g_count, reset tile ticket, detect int64-vs-int32 indices.
// ---------------------------------------------------------------------------
__global__ void init_kernel(const void* srcp, int n_edges, int n_nodes) {
    int i = blockIdx.x * blockDim.x + threadIdx.x;
    if (i < n_nodes) g_count[i] = 0;
    if (blockIdx.x == 0) {
        if (threadIdx.x == 0) { g_idx64 = 1; g_ticket = 0; }
        __syncthreads();
        int n = n_edges < 64 ? n_edges : 64;
        if (threadIdx.x < n) {
            long long v = ((const long long*)srcp)[threadIdx.x];
            if (v < 0 || v >= (long long)n_nodes) g_idx64 = 0;
        }
    }
}

// ---------------------------------------------------------------------------
// Histogram of dst degrees, 4 edges per thread.
// ---------------------------------------------------------------------------
__global__ void hist_kernel(const void* __restrict__ dstp, int n_edges) {
    int e0 = (blockIdx.x * blockDim.x + threadIdx.x) * 4;
    if (e0 >= n_edges) return;
    int d[4];
    int m = n_edges - e0; if (m > 4) m = 4;
    if (g_idx64) {
        const long long* dp = (const long long*)dstp;
        #pragma unroll
        for (int j = 0; j < 4; j++) d[j] = (int)dp[min(e0 + j, n_edges - 1)];
    } else {
        const int* dp = (const int*)dstp;
        #pragma unroll
        for (int j = 0; j < 4; j++) d[j] = dp[min(e0 + j, n_edges - 1)];
    }
    #pragma unroll
    for (int j = 0; j < 4; j++)
        if (j < m) atomicAdd(&g_count[d[j]], 1);
}

// ---------------------------------------------------------------------------
// Scan phase 1: per-1024-chunk reduce -> g_bsum. 49 blocks.
// ---------------------------------------------------------------------------
__global__ void scan_part1(int n_nodes) {
    __shared__ int s[256];
    int t = threadIdx.x;
    int base = blockIdx.x * SCAN_CHUNK + t * 4;
    int sum = 0;
    #pragma unroll
    for (int j = 0; j < 4; j++) {
        int i = base + j;
        if (i < n_nodes) sum += g_count[i];
    }
    s[t] = sum;
    __syncthreads();
    #pragma unroll
    for (int off = 128; off > 0; off >>= 1) {
        if (t < off) s[t] += s[t + off];
        __syncthreads();
    }
    if (t == 0) g_bsum[blockIdx.x] = s[0];
}

// ---------------------------------------------------------------------------
// Scan phase 2 (fused old part2+part3): each block redundantly computes its
// block-sum prefix (<=64 sums), then local scan, writes offsets/cursors.
// ---------------------------------------------------------------------------
__global__ void scan_part2(int n_nodes) {
    __shared__ int s[256];
    __shared__ int base_sh;
    int t = threadIdx.x;
    int b = blockIdx.x;

    // prefix of g_bsum[0..b)
    s[t] = (t < 64 && t < b) ? g_bsum[t] : 0;
    __syncthreads();
    if (t < 32) s[t] += s[t + 32];
    __syncthreads();
    if (t == 0) {
        int sum = 0;
        #pragma unroll
        for (int j = 0; j < 32; j++) sum += s[j];
        base_sh = sum;
    }
    __syncthreads();

    int base = b * SCAN_CHUNK + t * 4;
    int c[4], local = 0;
    #pragma unroll
    for (int j = 0; j < 4; j++) {
        int i = base + j;
        c[j] = (i < n_nodes) ? g_count[i] : 0;
        local += c[j];
    }
    s[t] = local;
    __syncthreads();
    #pragma unroll
    for (int off = 1; off < 256; off <<= 1) {
        int v = (t >= off) ? s[t - off] : 0;
        __syncthreads();
        s[t] += v;
        __syncthreads();
    }
    int run = base_sh + ((t == 0) ? 0 : s[t - 1]);
    #pragma unroll
    for (int j = 0; j < 4; j++) {
        int i = base + j;
        if (i < n_nodes) {
            g_offset[i] = run;
            g_cursor[i] = run;
            run += c[j];
            if (i == n_nodes - 1) g_offset[n_nodes] = run;
        }
    }
}

// ---------------------------------------------------------------------------
// Placement: bucket src ids by dst, 4 edges per thread.
// ---------------------------------------------------------------------------
__global__ void place_kernel(const void* __restrict__ srcp,
                             const void* __restrict__ dstp, int n_edges) {
    int e0 = (blockIdx.x * blockDim.x + threadIdx.x) * 4;
    if (e0 >= n_edges) return;
    int s[4], d[4];
    int m = n_edges - e0; if (m > 4) m = 4;
    if (g_idx64) {
        const long long* sp = (const long long*)srcp;
        const long long* dp = (const long long*)dstp;
        #pragma unroll
        for (int j = 0; j < 4; j++) {
            int e = min(e0 + j, n_edges - 1);
            s[j] = (int)sp[e]; d[j] = (int)dp[e];
        }
    } else {
        const int* sp = (const int*)srcp;
        const int* dp = (const int*)dstp;
        #pragma unroll
        for (int j = 0; j < 4; j++) {
            int e = min(e0 + j, n_edges - 1);
            s[j] = sp[e]; d[j] = dp[e];
        }
    }
    #pragma unroll
    for (int j = 0; j < 4; j++)
        if (j < m) {
            int pos = atomicAdd(&g_cursor[d[j]], 1);
            g_elist[pos] = s[j];
        }
}

// ---------------------------------------------------------------------------
// FUSED persistent kernel: gather (CSR, atomic-free) directly into the As
// smem tile, then tf32 mma + relu + residual. Dynamic tile ticket for load
// balance (output deterministic per tile). Each CTA fills the W tile once.
// 2 CTAs/SM: one CTA's MMA overlaps the other's gather.
// ---------------------------------------------------------------------------
__global__ __launch_bounds__(256, 2)
void gcn_fused_kernel(const float* __restrict__ x,
                      const float* __restrict__ W,
                      float* __restrict__ out,
                      int n_nodes, int n_tiles) {
    extern __shared__ float smem[];
    float* As = smem;                // [TROWS][SMS]
    float* Bs = smem + TROWS * SMS;  // [128][SMS]
    __shared__ int tile_sh;

    int tid = threadIdx.x;

    // Fill Bs (full W) once, rounding to tf32.
    #pragma unroll
    for (int i = tid; i < 128 * (D_DIM / 4); i += 256) {
        int r = i >> 5;
        int k = (i & 31) * 4;
        float4 b = *(const float4*)&W[r * D_DIM + k];
        uint32_t t;
        asm("cvt.rna.tf32.f32 %0, %1;" : "=r"(t) : "f"(b.x)); b.x = __uint_as_float(t);
        asm("cvt.rna.tf32.f32 %0, %1;" : "=r"(t) : "f"(b.y)); b.y = __uint_as_float(t);
        asm("cvt.rna.tf32.f32 %0, %1;" : "=r"(t) : "f"(b.z)); b.z = __uint_as_float(t);
        asm("cvt.rna.tf32.f32 %0, %1;" : "=r"(t) : "f"(b.w)); b.w = __uint_as_float(t);
        *(float4*)&Bs[r * SMS + k] = b;
    }

    int warp = tid >> 5;
    int lane = tid & 31;
    int g   = lane >> 2;
    int tig = lane & 3;
    int wr = (warp >> 2) * 32;
    int wc = (warp & 3) * 32;

    while (true) {
        __syncthreads();   // As/tile_sh reuse; first pass orders Bs fill
        if (tid == 0) tile_sh = atomicAdd(&g_ticket, 1);
        __syncthreads();
        int tile = tile_sh;
        if (tile >= n_tiles) break;
        int row0 = tile * TROWS;

        // ---- Gather phase: warp handles rows [warp*8, warp*8+8). ----
        #pragma unroll 1
        for (int rr = 0; rr < 8; rr++) {
            int r = warp * 8 + rr;
            int row = row0 + r;
            float4 acc = make_float4(0.f, 0.f, 0.f, 0.f);
            if (row < n_nodes) {
                int beg = g_offset[row];
                int end = g_offset[row + 1];
                int i = beg;
                for (; i + 8 <= end; i += 8) {
                    int s[8];
                    #pragma unroll
                    for (int j = 0; j < 8; j++) s[j] = __ldg(&g_elist[i + j]);
                    float4 v[8];
                    #pragma unroll
                    for (int j = 0; j < 8; j++)
                        v[j] = ((const float4*)(x + (long long)s[j] * D_DIM))[lane];
                    #pragma unroll
                    for (int j = 0; j < 8; j++) {
                        acc.x += v[j].x; acc.y += v[j].y;
                        acc.z += v[j].z; acc.w += v[j].w;
                    }
                }
                if (i + 4 <= end) {
                    int s[4];
                    #pragma unroll
                    for (int j = 0; j < 4; j++) s[j] = __ldg(&g_elist[i + j]);
                    float4 v[4];
                    #pragma unroll
                    for (int j = 0; j < 4; j++)
                        v[j] = ((const float4*)(x + (long long)s[j] * D_DIM))[lane];
                    #pragma unroll
                    for (int j = 0; j < 4; j++) {
                        acc.x += v[j].x; acc.y += v[j].y;
                        acc.z += v[j].z; acc.w += v[j].w;
                    }
                    i += 4;
                }
                for (; i < end; i++) {
                    int s0 = __ldg(&g_elist[i]);
                    float4 v0 = ((const float4*)(x + (long long)s0 * D_DIM))[lane];
                    acc.x += v0.x; acc.y += v0.y; acc.z += v0.z; acc.w += v0.w;
                }
            }
            uint32_t t;
            asm("cvt.rna.tf32.f32 %0, %1;" : "=r"(t) : "f"(acc.x)); acc.x = __uint_as_float(t);
            asm("cvt.rna.tf32.f32 %0, %1;" : "=r"(t) : "f"(acc.y)); acc.y = __uint_as_float(t);
            asm("cvt.rna.tf32.f32 %0, %1;" : "=r"(t) : "f"(acc.z)); acc.z = __uint_as_float(t);
            asm("cvt.rna.tf32.f32 %0, %1;" : "=r"(t) : "f"(acc.w)); acc.w = __uint_as_float(t);
            *(float4*)&As[r * SMS + lane * 4] = acc;
        }
        __syncthreads();

        // ---- MMA mainloop. ----
        float acc[2][4][4];
        #pragma unroll
        for (int mi = 0; mi < 2; mi++)
            #pragma unroll
            for (int ni = 0; ni < 4; ni++)
                #pragma unroll
                for (int c = 0; c < 4; c++) acc[mi][ni][c] = 0.f;

        #pragma unroll 4
        for (int k0 = 0; k0 < D_DIM; k0 += 8) {
            uint32_t a[2][4], b[4][2];
            #pragma unroll
            for (int mi = 0; mi < 2; mi++) {
                const float* base = &As[(wr + mi * 16 + g) * SMS + k0 + tig];
                a[mi][0] = __float_as_uint(base[0]);
                a[mi][1] = __float_as_uint(base[8 * SMS]);
                a[mi][2] = __float_as_uint(base[4]);
                a[mi][3] = __float_as_uint(base[8 * SMS + 4]);
            }
            #pragma unroll
            for (int ni = 0; ni < 4; ni++) {
                const float* base = &Bs[(wc + ni * 8 + g) * SMS + k0 + tig];
                b[ni][0] = __float_as_uint(base[0]);
                b[ni][1] = __float_as_uint(base[4]);
            }
            #pragma unroll
            for (int mi = 0; mi < 2; mi++)
                #pragma unroll
                for (int ni = 0; ni < 4; ni++) {
                    asm volatile(
                        "mma.sync.aligned.m16n8k8.row.col.f32.tf32.tf32.f32 "
                        "{%0,%1,%2,%3}, {%4,%5,%6,%7}, {%8,%9}, {%0,%1,%2,%3};"
                        : "+f"(acc[mi][ni][0]), "+f"(acc[mi][ni][1]),
                          "+f"(acc[mi][ni][2]), "+f"(acc[mi][ni][3])
                        : "r"(a[mi][0]), "r"(a[mi][1]), "r"(a[mi][2]), "r"(a[mi][3]),
                          "r"(b[ni][0]), "r"(b[ni][1]));
                }
        }

        // ---- Epilogue: relu + residual. ----
        #pragma unroll
        for (int mi = 0; mi < 2; mi++) {
            #pragma unroll
            for (int half = 0; half < 2; half++) {
                int row = row0 + wr + mi * 16 + g + half * 8;
                if (row < n_nodes) {
                    #pragma unroll
                    for (int ni = 0; ni < 4; ni++) {
                        int col = wc + ni * 8 + tig * 2;
                        long long base = (long long)row * D_DIM + col;
                        float2 xr = *(const float2*)&x[base];
                        float2 o;
                        o.x = fmaxf(acc[mi][ni][half * 2 + 0], 0.f) + xr.x;
                        o.y = fmaxf(acc[mi][ni][half * 2 + 1], 0.f) + xr.y;
                        *(float2*)&out[base] = o;
                    }
                }
            }
        }
    }
}

// ---------------------------------------------------------------------------
extern "C" void kernel_launch(void* const* d_in, const int* in_sizes, int n_in,
                              void* d_out, int out_size) {
    const float* x   = (const float*)d_in[0];
    const void*  src = d_in[1];
    const void*  dst = d_in[2];
    const float* W   = (const float*)d_in[3];
    float* out = (float*)d_out;

    int n_nodes = in_sizes[0] / D_DIM;
    int n_edges = in_sizes[1];

    static const size_t smem_bytes = (TROWS + 128) * SMS * sizeof(float); // ~101KB
    cudaFuncSetAttribute(gcn_fused_kernel,
                         cudaFuncAttributeMaxDynamicSharedMemorySize,
                         (int)smem_bytes);

    // 1. Init: zero counts, reset ticket, detect index dtype.
    init_kernel<<<(n_nodes + 255) / 256, 256>>>(src, n_edges, n_nodes);

    // 2. CSR build: histogram -> 2-phase device-wide scan -> placement.
    int e4blocks = (n_edges + 4 * 256 - 1) / (4 * 256);
    hist_kernel<<<e4blocks, 256>>>(dst, n_edges);
    int sblocks = (n_nodes + SCAN_CHUNK - 1) / SCAN_CHUNK;   // 49
    scan_part1<<<sblocks, 256>>>(n_nodes);
    scan_part2<<<sblocks, 256>>>(n_nodes);
    place_kernel<<<e4blocks, 256>>>(src, dst, n_edges);

    // 3. Fused gather + tf32 GEMM + ReLU + residual (persistent, ticketed).
    {
        int n_tiles = (n_nodes + TROWS - 1) / TROWS;
        int grid = GEMM_GRID < n_tiles ? GEMM_GRID : n_tiles;
        gcn_fused_kernel<<<grid, 256, smem_bytes>>>(x, W, out, n_nodes, n_tiles);
    }
}